// round 16
// baseline (speedup 1.0000x reference)
#include <cuda_runtime.h>
#include <cuda_fp16.h>
#include <cstdint>

#define TOK 16384
#define TPAD 16640
#define DD 2048
#define FF 5632
#define STAGE 49152
#define NT1 44   // FF/128
#define NT2 8    // DD/256

// ---------------- device scratch ----------------
__device__ int g_meta[8];          // 0 cnt0, 1 cnt1, 4 M0pad, 5 Mtot
__device__ int g_rows[TPAD];
__device__ __align__(128) __half g_Xh[(size_t)TPAD * DD];
__device__ __align__(128) __half g_Wg[(size_t)2 * DD * FF];   // native [e][D][FF] fp16
__device__ __align__(128) __half g_Wu[(size_t)2 * DD * FF];
__device__ __align__(128) __half g_Wd[(size_t)2 * FF * DD];   // native [e][FF][D] fp16
__device__ __align__(128) __half g_Hh[(size_t)TPAD * FF];

// ---------------- helpers ----------------
__device__ __forceinline__ uint32_t sptr(const void* p) {
    uint32_t a;
    asm("{.reg .u64 t; cvta.to.shared.u64 t,%1; cvt.u32.u64 %0,t;}" : "=r"(a) : "l"(p));
    return a;
}
__device__ __forceinline__ void cpa(uint32_t d, const void* s) {
    asm volatile("cp.async.cg.shared.global [%0],[%1],16;" :: "r"(d), "l"(s));
}
__device__ __forceinline__ void cpcommit() { asm volatile("cp.async.commit_group;"); }
template <int N> __device__ __forceinline__ void cpwait() {
    asm volatile("cp.async.wait_group %0;" :: "n"(N));
}
__device__ __forceinline__ uint32_t sw(uint32_t o) { return o ^ ((o >> 3) & 0x70); }
__device__ __forceinline__ void ldsm4(uint32_t* r, uint32_t a) {
    asm volatile("ldmatrix.sync.aligned.m8n8.x4.shared.b16 {%0,%1,%2,%3},[%4];"
                 : "=r"(r[0]), "=r"(r[1]), "=r"(r[2]), "=r"(r[3]) : "r"(a));
}
__device__ __forceinline__ void ldsm4t(uint32_t* r, uint32_t a) {
    asm volatile("ldmatrix.sync.aligned.m8n8.x4.trans.shared.b16 {%0,%1,%2,%3},[%4];"
                 : "=r"(r[0]), "=r"(r[1]), "=r"(r[2]), "=r"(r[3]) : "r"(a));
}
__device__ __forceinline__ void mma(float* c, const uint32_t* a, uint32_t b0, uint32_t b1) {
    asm volatile("mma.sync.aligned.m16n8k16.row.col.f32.f16.f16.f32 "
                 "{%0,%1,%2,%3},{%4,%5,%6,%7},{%8,%9},{%0,%1,%2,%3};"
                 : "+f"(c[0]), "+f"(c[1]), "+f"(c[2]), "+f"(c[3])
                 : "r"(a[0]), "r"(a[1]), "r"(a[2]), "r"(a[3]), "r"(b0), "r"(b1));
}

// ---------------- streaming fp32 -> fp16 convert (no transpose) ----------------
__global__ void k_cvt(const float* src, __half* dst, int n8) {
    int i = blockIdx.x * 256 + threadIdx.x;
    if (i >= n8) return;
    const float4* s = (const float4*)src + (size_t)i * 2;
    float4 a = s[0], b = s[1];
    uint4 o;
    __half2 h;
    h = __halves2half2(__float2half_rn(a.x), __float2half_rn(a.y)); o.x = *(uint32_t*)&h;
    h = __halves2half2(__float2half_rn(a.z), __float2half_rn(a.w)); o.y = *(uint32_t*)&h;
    h = __halves2half2(__float2half_rn(b.x), __float2half_rn(b.y)); o.z = *(uint32_t*)&h;
    h = __halves2half2(__float2half_rn(b.z), __float2half_rn(b.w)); o.w = *(uint32_t*)&h;
    ((uint4*)dst)[i] = o;
}

// ---------------- routing: single block, deterministic scan ----------------
__global__ void __launch_bounds__(1024, 1) k_route(const int* mask) {
    int tid = threadIdx.x, lane = tid & 31, w = tid >> 5;
    __shared__ int wsum[32];
    int base = tid * 16;
    int loc[16];
    int s = 0;
    #pragma unroll
    for (int i = 0; i < 16; i++) { int e = mask[base + i] != 0; loc[i] = s; s += e; }
    int ts_own = s;
    int v = s;
    #pragma unroll
    for (int o = 1; o < 32; o <<= 1) { int n = __shfl_up_sync(~0u, v, o); if (lane >= o) v += n; }
    if (lane == 31) wsum[w] = v;
    __syncthreads();
    if (w == 0) {
        int x = wsum[lane];
        #pragma unroll
        for (int o = 1; o < 32; o <<= 1) { int n = __shfl_up_sync(~0u, x, o); if (lane >= o) x += n; }
        wsum[lane] = x;
    }
    __syncthreads();
    int total1 = wsum[31];
    int thread_excl = (w == 0 ? 0 : wsum[w - 1]) + v - ts_own;
    int cnt0 = TOK - total1;
    int m0 = (cnt0 + 127) & ~127, m1 = (total1 + 127) & ~127;
    if (tid == 0) {
        g_meta[0] = cnt0; g_meta[1] = total1; g_meta[4] = m0; g_meta[5] = m0 + m1;
    }
    #pragma unroll
    for (int i = 0; i < 16; i++) {
        int t = base + i;
        int e = mask[t] != 0;
        int p1 = thread_excl + loc[i];
        int row = e ? m0 + p1 : t - p1;
        g_rows[row] = t;
    }
    for (int r = cnt0 + tid; r < m0; r += 1024) g_rows[r] = -1;
    for (int r = m0 + total1 + tid; r < m0 + m1; r += 1024) g_rows[r] = -1;
}

__global__ void k_xsplit(const float* X) {
    size_t i = (size_t)blockIdx.x * 256 + threadIdx.x;
    size_t row = i / (DD / 4);
    int c4 = (int)(i % (DD / 4));
    if (row >= (size_t)g_meta[5]) return;
    int t = g_rows[row];
    float4 v = t >= 0 ? ((const float4*)X)[(size_t)t * (DD / 4) + c4] : make_float4(0, 0, 0, 0);
    size_t o = row * DD + (size_t)c4 * 4;
    *(__half2*)(g_Xh + o) = __halves2half2(__float2half_rn(v.x), __float2half_rn(v.y));
    *(__half2*)(g_Xh + o + 2) = __halves2half2(__float2half_rn(v.z), __float2half_rn(v.w));
}

// ---------------- chunk loader ----------------
// A: 128 rows x 128B (K-major, sw128) @0.
// B: 64 k-rows x 512B (native [k][n], chunk-XOR swizzle) @16K.
// B cols 0-127 from B0, 128-255 from B1 (GEMM2: B1 = B0+128 -> contiguous 256).
__device__ __forceinline__ void load_chunk(uint32_t st, int tid,
                                           const __half* A0, const __half* B0, const __half* B1,
                                           int lda, int ldb, int k0) {
    #pragma unroll
    for (int i = tid; i < 1024; i += 512) {
        int r = i >> 3, u = i & 7;
        cpa(st + sw(r * 128 + u * 16), A0 + (size_t)r * lda + k0 + u * 8);
    }
    #pragma unroll
    for (int i = tid; i < 2048; i += 512) {
        int r = i >> 5, c = i & 31;
        const __half* s = (c < 16) ? B0 + (size_t)(k0 + r) * ldb + c * 8
                                   : B1 + (size_t)(k0 + r) * ldb + (c - 16) * 8;
        cpa(st + 16384 + r * 512 + ((c ^ (r & 31)) * 16), s);
    }
    cpcommit();
}

// ---------------- GEMM1: persistent, X @ {Wg,Wu} -> SwiGLU -> H ----------------
__global__ void __launch_bounds__(512, 1) k_gemm1() {
    extern __shared__ __align__(1024) char smem[];
    uint32_t sb = sptr(smem);
    int M0p = g_meta[4], Mtot = g_meta[5];
    int total = NT1 * (Mtot >> 7);
    int tid = threadIdx.x, lane = tid & 31, wid = tid >> 5;
    int mw = wid & 3, nw = wid >> 2;
    // B-fragment addressing (trans-ldsm from [k][n]):
    int kkb = (lane & 7) + ((lane >> 3) & 1) * 8;          // k within 16
    int cnb = ((lane >> 4) & 1);                            // +1 chunk for n8-15
    int cn4[4] = {nw * 4 + cnb, nw * 4 + 2 + cnb, 16 + nw * 4 + cnb, 16 + nw * 4 + 2 + cnb};
    int ar = mw * 32 + (lane & 7) + ((lane >> 3) & 1) * 8;
    int akb = ((lane >> 4) & 1) * 16;
    const int NK = DD / 64;

    int tl = blockIdx.x;
    if (tl >= total) return;
    const __half *A0, *B0, *B1, *A0n, *B0n, *B1n;
    {
        int nt = tl % NT1, mt = tl / NT1;
        int e = (mt * 128 >= M0p);
        A0 = g_Xh + (size_t)mt * 128 * DD;
        B0 = g_Wg + (size_t)e * DD * FF + nt * 128;
        B1 = g_Wu + (size_t)e * DD * FF + nt * 128;
    }
    load_chunk(sb, tid, A0, B0, B1, DD, FF, 0);

    while (true) {
        float acc[2][8][4];
        #pragma unroll
        for (int a = 0; a < 2; a++)
            #pragma unroll
            for (int j = 0; j < 8; j++)
                #pragma unroll
                for (int q = 0; q < 4; q++) acc[a][j][q] = 0.f;
        int tln = tl + gridDim.x;
        bool have_next = tln < total;
        if (have_next) {
            int nt = tln % NT1, mt = tln / NT1;
            int e = (mt * 128 >= M0p);
            A0n = g_Xh + (size_t)mt * 128 * DD;
            B0n = g_Wg + (size_t)e * DD * FF + nt * 128;
            B1n = g_Wu + (size_t)e * DD * FF + nt * 128;
        }
        for (int kc = 0; kc < NK; kc++) {
            if (kc + 1 < NK) { load_chunk(sb + ((kc + 1) & 1) * STAGE, tid, A0, B0, B1, DD, FF, (kc + 1) * 64); cpwait<1>(); }
            else if (have_next) { load_chunk(sb, tid, A0n, B0n, B1n, DD, FF, 0); cpwait<1>(); }
            else cpwait<0>();
            __syncthreads();
            uint32_t st = sb + (kc & 1) * STAGE;
            #pragma unroll
            for (int ks = 0; ks < 4; ks++) {
                uint32_t ah0[4], ah1[4];
                int kb = ks * 32;
                ldsm4(ah0, st + sw(ar * 128 + kb + akb));
                ldsm4(ah1, st + sw((ar + 16) * 128 + kb + akb));
                int kk = ks * 16 + kkb;
                uint32_t brow = st + 16384 + kk * 512;
                int kx = kk & 31;
                #pragma unroll
                for (int p = 0; p < 4; p++) {
                    uint32_t bb[4];
                    ldsm4t(bb, brow + ((cn4[p] ^ kx) * 16));
                    #pragma unroll
                    for (int h = 0; h < 2; h++) {
                        int j = 2 * p + h;
                        mma(acc[0][j], ah0, bb[2 * h], bb[2 * h + 1]);
                        mma(acc[1][j], ah1, bb[2 * h], bb[2 * h + 1]);
                    }
                }
            }
            __syncthreads();   // WAR guard
        }
        // epilogue
        {
            int nt = tl % NT1, mtb = (tl / NT1) * 128;
            #pragma unroll
            for (int mt = 0; mt < 2; mt++)
                #pragma unroll
                for (int jg = 0; jg < 4; jg++) {
                    int row = mtb + mw * 32 + mt * 16 + (lane >> 2);
                    int col = nt * 128 + nw * 32 + jg * 8 + (lane & 3) * 2;
                    #pragma unroll
                    for (int h = 0; h < 2; h++) {
                        float g0 = acc[mt][jg][2 * h], g1 = acc[mt][jg][2 * h + 1];
                        float u0 = acc[mt][jg + 4][2 * h], u1 = acc[mt][jg + 4][2 * h + 1];
                        float v0 = g0 * u0 / (1.f + __expf(-g0));
                        float v1 = g1 * u1 / (1.f + __expf(-g1));
                        size_t o = (size_t)(row + h * 8) * FF + col;
                        *(__half2*)(g_Hh + o) =
                            __halves2half2(__float2half_rn(v0), __float2half_rn(v1));
                    }
                }
        }
        if (!have_next) break;
        tl = tln; A0 = A0n; B0 = B0n; B1 = B1n;
    }
}

// ---------------- GEMM2: persistent, H @ Wd -> scatter fp32 ----------------
__global__ void __launch_bounds__(512, 1) k_gemm2(float* out) {
    extern __shared__ __align__(1024) char smem[];
    uint32_t sb = sptr(smem);
    int M0p = g_meta[4], Mtot = g_meta[5];
    int total = NT2 * (Mtot >> 7);
    int tid = threadIdx.x, lane = tid & 31, wid = tid >> 5;
    int mw = wid & 3, nw = wid >> 2;
    int kkb = (lane & 7) + ((lane >> 3) & 1) * 8;
    int cnb = ((lane >> 4) & 1);
    int cn4[4] = {nw * 8 + cnb, nw * 8 + 2 + cnb, nw * 8 + 4 + cnb, nw * 8 + 6 + cnb};
    int ar = mw * 32 + (lane & 7) + ((lane >> 3) & 1) * 8;
    int akb = ((lane >> 4) & 1) * 16;
    const int NK = FF / 64;

    int tl = blockIdx.x;
    if (tl >= total) return;
    const __half *A0, *B0, *A0n, *B0n;
    {
        int nt = tl & (NT2 - 1), mt = tl >> 3;
        int e = (mt * 128 >= M0p);
        A0 = g_Hh + (size_t)mt * 128 * FF;
        B0 = g_Wd + (size_t)e * FF * DD + nt * 256;
    }
    load_chunk(sb, tid, A0, B0, B0 + 128, FF, DD, 0);

    while (true) {
        float acc[2][8][4];
        #pragma unroll
        for (int a = 0; a < 2; a++)
            #pragma unroll
            for (int j = 0; j < 8; j++)
                #pragma unroll
                for (int q = 0; q < 4; q++) acc[a][j][q] = 0.f;
        int tln = tl + gridDim.x;
        bool have_next = tln < total;
        if (have_next) {
            int nt = tln & (NT2 - 1), mt = tln >> 3;
            int e = (mt * 128 >= M0p);
            A0n = g_Hh + (size_t)mt * 128 * FF;
            B0n = g_Wd + (size_t)e * FF * DD + nt * 256;
        }
        for (int kc = 0; kc < NK; kc++) {
            if (kc + 1 < NK) { load_chunk(sb + ((kc + 1) & 1) * STAGE, tid, A0, B0, B0 + 128, FF, DD, (kc + 1) * 64); cpwait<1>(); }
            else if (have_next) { load_chunk(sb, tid, A0n, B0n, B0n + 128, FF, DD, 0); cpwait<1>(); }
            else cpwait<0>();
            __syncthreads();
            uint32_t st = sb + (kc & 1) * STAGE;
            #pragma unroll
            for (int ks = 0; ks < 4; ks++) {
                uint32_t ah0[4], ah1[4];
                int kb = ks * 32;
                ldsm4(ah0, st + sw(ar * 128 + kb + akb));
                ldsm4(ah1, st + sw((ar + 16) * 128 + kb + akb));
                int kk = ks * 16 + kkb;
                uint32_t brow = st + 16384 + kk * 512;
                int kx = kk & 31;
                #pragma unroll
                for (int p = 0; p < 4; p++) {
                    uint32_t bb[4];
                    ldsm4t(bb, brow + ((cn4[p] ^ kx) * 16));
                    #pragma unroll
                    for (int h = 0; h < 2; h++) {
                        int j = 2 * p + h;
                        mma(acc[0][j], ah0, bb[2 * h], bb[2 * h + 1]);
                        mma(acc[1][j], ah1, bb[2 * h], bb[2 * h + 1]);
                    }
                }
            }
            __syncthreads();   // WAR guard
        }
        // epilogue: scatter
        {
            int nt = tl & (NT2 - 1), mtb = (tl >> 3) * 128;
            #pragma unroll
            for (int mt = 0; mt < 2; mt++) {
                int row = mtb + mw * 32 + mt * 16 + (lane >> 2);
                #pragma unroll
                for (int h = 0; h < 2; h++) {
                    int t = g_rows[row + h * 8];
                    if (t < 0) continue;
                    #pragma unroll
                    for (int j = 0; j < 8; j++) {
                        int col = nt * 256 + nw * 64 + j * 8 + (lane & 3) * 2;
                        float2 v = make_float2(acc[mt][j][2 * h], acc[mt][j][2 * h + 1]);
                        *(float2*)(out + (size_t)t * DD + col) = v;
                    }
                }
            }
        }
        if (!have_next) break;
        tl = tln; A0 = A0n; B0 = B0n;
    }
}

// ---------------- launch ----------------
extern "C" void kernel_launch(void* const* d_in, const int* in_sizes, int n_in,
                              void* d_out, int out_size) {
    const float* X = (const float*)d_in[0];
    const int* mask = (const int*)d_in[1];
    const float* wg = (const float*)d_in[2];
    const float* wu = (const float*)d_in[3];
    const float* wd = (const float*)d_in[4];
    float* out = (float*)d_out;

    cudaFuncSetAttribute(k_gemm1, cudaFuncAttributeMaxDynamicSharedMemorySize, 2 * STAGE);
    cudaFuncSetAttribute(k_gemm2, cudaFuncAttributeMaxDynamicSharedMemorySize, 2 * STAGE);

    int nsm = 148;
    cudaDeviceGetAttribute(&nsm, cudaDevAttrMultiProcessorCount, 0);

    void *pWg, *pWu, *pWd;
    cudaGetSymbolAddress(&pWg, g_Wg);
    cudaGetSymbolAddress(&pWu, g_Wu);
    cudaGetSymbolAddress(&pWd, g_Wd);

    const int n8 = (int)((size_t)2 * DD * FF / 8);
    const int cvb = (n8 + 255) / 256;
    k_cvt<<<cvb, 256>>>(wg, (__half*)pWg, n8);
    k_cvt<<<cvb, 256>>>(wu, (__half*)pWu, n8);
    k_cvt<<<cvb, 256>>>(wd, (__half*)pWd, n8);
    k_route<<<1, 1024>>>(mask);
    k_xsplit<<<(int)(((size_t)TPAD * DD / 4 + 255) / 256), 256>>>(X);
    k_gemm1<<<nsm, 512, 2 * STAGE>>>();
    k_gemm2<<<nsm, 512, 2 * STAGE>>>(out);
}

// round 17
// speedup vs baseline: 1.6789x; 1.6789x over previous
#include <cuda_runtime.h>
#include <cuda_fp16.h>
#include <cstdint>

#define TOK 16384
#define TPAD 16640
#define DD 2048
#define FF 5632
#define STAGE 49152

// ---------------- device scratch ----------------
__device__ int g_meta[8];          // 0 cnt0, 1 cnt1, 2 pos0, 3 pos1, 4 M0pad, 5 Mtot
__device__ int g_rows[TPAD];
__device__ __align__(128) __half g_Xh[(size_t)TPAD * DD];
__device__ __align__(128) __half g_Wg[(size_t)2 * FF * DD];   // [e][FF][D] K-major
__device__ __align__(128) __half g_Wu[(size_t)2 * FF * DD];
__device__ __align__(128) __half g_Wd[(size_t)2 * DD * FF];   // [e][D][FF] K-major
__device__ __align__(128) __half g_Hh[(size_t)TPAD * FF];

// ---------------- helpers ----------------
__device__ __forceinline__ uint32_t sptr(const void* p) {
    uint32_t a;
    asm("{.reg .u64 t; cvta.to.shared.u64 t,%1; cvt.u32.u64 %0,t;}" : "=r"(a) : "l"(p));
    return a;
}
__device__ __forceinline__ void cpa(uint32_t d, const void* s) {
    asm volatile("cp.async.cg.shared.global [%0],[%1],16;" :: "r"(d), "l"(s));
}
__device__ __forceinline__ void cpcommit() { asm volatile("cp.async.commit_group;"); }
template <int N> __device__ __forceinline__ void cpwait() {
    asm volatile("cp.async.wait_group %0;" :: "n"(N));
}
__device__ __forceinline__ uint32_t sw(uint32_t o) { return o ^ ((o >> 3) & 0x70); }
__device__ __forceinline__ void ldsm4(uint32_t* r, uint32_t a) {
    asm volatile("ldmatrix.sync.aligned.m8n8.x4.shared.b16 {%0,%1,%2,%3},[%4];"
                 : "=r"(r[0]), "=r"(r[1]), "=r"(r[2]), "=r"(r[3]) : "r"(a));
}
__device__ __forceinline__ void mma(float* c, const uint32_t* a, uint32_t b0, uint32_t b1) {
    asm volatile("mma.sync.aligned.m16n8k16.row.col.f32.f16.f16.f32 "
                 "{%0,%1,%2,%3},{%4,%5,%6,%7},{%8,%9},{%0,%1,%2,%3};"
                 : "+f"(c[0]), "+f"(c[1]), "+f"(c[2]), "+f"(c[3])
                 : "r"(a[0]), "r"(a[1]), "r"(a[2]), "r"(a[3]), "r"(b0), "r"(b1));
}

// ---------------- routing (low-atomic-contention, r11) ----------------
__global__ void k_init() {
    int i = blockIdx.x * 256 + threadIdx.x;
    if (i < TPAD) g_rows[i] = -1;
    if (i < 8) g_meta[i] = 0;
}
__global__ void k_count(const int* mask) {
    int tid = threadIdx.x;
    int t = blockIdx.x * 256 + tid;
    int e = mask[t] != 0;
    unsigned b1 = __ballot_sync(0xFFFFFFFFu, e);
    __shared__ int wc[8];
    if ((tid & 31) == 0) wc[tid >> 5] = __popc(b1);
    __syncthreads();
    if (tid == 0) {
        int c1 = 0;
        #pragma unroll
        for (int i = 0; i < 8; i++) c1 += wc[i];
        atomicAdd(&g_meta[1], c1);
        atomicAdd(&g_meta[0], 256 - c1);
    }
}
__global__ void k_metak() {
    int m0 = (g_meta[0] + 127) & ~127, m1 = (g_meta[1] + 127) & ~127;
    g_meta[4] = m0; g_meta[5] = m0 + m1; g_meta[2] = 0; g_meta[3] = m0;
}
__global__ void k_assign(const int* mask) {
    int tid = threadIdx.x, lane = tid & 31, w = tid >> 5;
    int t = blockIdx.x * 256 + tid;
    int e = mask[t] != 0;
    unsigned b1 = __ballot_sync(0xFFFFFFFFu, e);
    __shared__ int s1[8], sb[2];
    if (lane == 0) s1[w] = __popc(b1);
    __syncthreads();
    if (tid == 0) {
        int acc = 0;
        #pragma unroll
        for (int i = 0; i < 8; i++) { int c = s1[i]; s1[i] = acc; acc += c; }
        sb[1] = atomicAdd(&g_meta[3], acc);
        sb[0] = atomicAdd(&g_meta[2], 256 - acc);
    }
    __syncthreads();
    unsigned lt = (1u << lane) - 1u;
    int r1 = __popc(b1 & lt);
    int row = e ? sb[1] + s1[w] + r1
                : sb[0] + 32 * w - s1[w] + (lane - r1);
    g_rows[row] = t;
}
__global__ void k_xsplit(const float* X) {
    size_t i = (size_t)blockIdx.x * 256 + threadIdx.x;
    size_t row = i / (DD / 4);
    int c4 = (int)(i % (DD / 4));
    if (row >= (size_t)g_meta[5]) return;
    int t = g_rows[row];
    float4 v = t >= 0 ? ((const float4*)X)[(size_t)t * (DD / 4) + c4] : make_float4(0, 0, 0, 0);
    size_t o = row * DD + (size_t)c4 * 4;
    *(__half2*)(g_Xh + o) = __halves2half2(__float2half_rn(v.x), __float2half_rn(v.y));
    *(__half2*)(g_Xh + o + 2) = __halves2half2(__float2half_rn(v.z), __float2half_rn(v.w));
}

// ---------------- fast transpose+convert: fp32 [R,C] -> fp16 [C,R] ----------------
// 64x64 tiles, 256 threads, float4 loads, uint4 (8-half) stores.
__global__ void __launch_bounds__(256) k_tr(const float* src, __half* dst, int R, int C) {
    __shared__ float t[64][65];
    size_t eo = (size_t)blockIdx.z * R * C;
    src += eo; dst += eo;
    int r0 = blockIdx.y * 64, c0 = blockIdx.x * 64;
    int tid = threadIdx.x;
    #pragma unroll
    for (int i = tid; i < 1024; i += 256) {
        int r = i >> 4, c4 = i & 15;
        float4 v = *(const float4*)(src + (size_t)(r0 + r) * C + c0 + c4 * 4);
        t[r][c4 * 4 + 0] = v.x; t[r][c4 * 4 + 1] = v.y;
        t[r][c4 * 4 + 2] = v.z; t[r][c4 * 4 + 3] = v.w;
    }
    __syncthreads();
    #pragma unroll
    for (int i = tid; i < 512; i += 256) {
        int c = i >> 3, rg = i & 7;
        __half2 h[4];
        #pragma unroll
        for (int q = 0; q < 4; q++)
            h[q] = __halves2half2(__float2half_rn(t[rg * 8 + q * 2][c]),
                                  __float2half_rn(t[rg * 8 + q * 2 + 1][c]));
        *(uint4*)(dst + (size_t)(c0 + c) * R + r0 + rg * 8) = *(uint4*)h;
    }
}

// ---------------- shared GEMM core (r11 best-measured) ----------------
// 512 threads, 16 warps (4m x 4n), warptile 32x64.
// smem stage (48KB): A[128x64h]@0, B[256x64h]@16K. 2 stages.
__device__ __forceinline__ void gemm_main(
    const __half* A0, const __half* B0, const __half* B1,
    int lda, int ldb, int NK, uint32_t sb, int tid, const int* pb,
    float acc[2][8][4])
{
    int lane = tid & 31, wid = tid >> 5, mw = wid & 3;
    #pragma unroll
    for (int a = 0; a < 2; a++)
        #pragma unroll
        for (int j = 0; j < 8; j++)
            #pragma unroll
            for (int q = 0; q < 4; q++) acc[a][j][q] = 0.f;

    auto load = [&](int kc) {
        uint32_t st = sb + (kc & 1) * STAGE;
        int k0 = kc * 64;
        #pragma unroll
        for (int i = tid; i < 1024; i += 512) {
            int r = i >> 3, u = i & 7;
            cpa(st + sw(r * 128 + u * 16), A0 + (size_t)r * lda + k0 + u * 8);
        }
        #pragma unroll
        for (int i = tid; i < 2048; i += 512) {
            int r = i >> 3, u = i & 7;
            const __half* s = (r < 128) ? B0 + (size_t)r * ldb + k0 + u * 8
                                        : B1 + (size_t)(r - 128) * ldb + k0 + u * 8;
            cpa(st + 16384 + sw(r * 128 + u * 16), s);
        }
        cpcommit();
    };

    load(0);
    int ar = mw * 32 + (lane & 7) + ((lane >> 3) & 1) * 8;
    int akb = ((lane >> 4) & 1) * 16;
    int br = (lane & 7) + ((lane >> 4) & 1) * 8;
    int bkb = ((lane >> 3) & 1) * 16;

    for (int kc = 0; kc < NK; kc++) {
        if (kc + 1 < NK) { load(kc + 1); cpwait<1>(); }
        else cpwait<0>();
        __syncthreads();
        uint32_t st = sb + (kc & 1) * STAGE;
        #pragma unroll
        for (int ks = 0; ks < 4; ks++) {
            uint32_t ah0[4], ah1[4];
            int kb = ks * 32;
            ldsm4(ah0, st + sw(ar * 128 + kb + akb));
            ldsm4(ah1, st + sw((ar + 16) * 128 + kb + akb));
            #pragma unroll
            for (int p = 0; p < 4; p++) {
                uint32_t bb[4];
                ldsm4(bb, st + 16384 + sw((pb[p] + br) * 128 + kb + bkb));
                #pragma unroll
                for (int h = 0; h < 2; h++) {
                    int j = 2 * p + h;
                    mma(acc[0][j], ah0, bb[2 * h], bb[2 * h + 1]);
                    mma(acc[1][j], ah1, bb[2 * h], bb[2 * h + 1]);
                }
            }
        }
        __syncthreads();
    }
}

// ---------------- GEMM1: X @ {Wg,Wu}^T -> SwiGLU -> H ----------------
__global__ void __launch_bounds__(512, 1) k_gemm1() {
    extern __shared__ __align__(1024) char smem[];
    int nt = blockIdx.x, mtb = blockIdx.y * 128;
    if (mtb >= g_meta[5]) return;
    int e = (mtb >= g_meta[4]) ? 1 : 0;
    int tid = threadIdx.x, lane = tid & 31, wid = tid >> 5;
    int mw = wid & 3, nw = wid >> 2;
    int pb[4] = {nw * 32, nw * 32 + 16, 128 + nw * 32, 128 + nw * 32 + 16};
    float acc[2][8][4];
    gemm_main(g_Xh + (size_t)mtb * DD,
              g_Wg + ((size_t)e * FF + (size_t)nt * 128) * DD,
              g_Wu + ((size_t)e * FF + (size_t)nt * 128) * DD,
              DD, DD, DD / 64, sptr(smem), tid, pb, acc);
    // epilogue: j 0-3 gate, j 4-7 up (same cols)
    #pragma unroll
    for (int mt = 0; mt < 2; mt++)
        #pragma unroll
        for (int jg = 0; jg < 4; jg++) {
            int row = mtb + mw * 32 + mt * 16 + (lane >> 2);
            int col = nt * 128 + nw * 32 + jg * 8 + (lane & 3) * 2;
            #pragma unroll
            for (int h = 0; h < 2; h++) {
                float g0 = acc[mt][jg][2 * h], g1 = acc[mt][jg][2 * h + 1];
                float u0 = acc[mt][jg + 4][2 * h], u1 = acc[mt][jg + 4][2 * h + 1];
                float v0 = g0 * u0 / (1.f + __expf(-g0));
                float v1 = g1 * u1 / (1.f + __expf(-g1));
                size_t o = (size_t)(row + h * 8) * FF + col;
                *(__half2*)(g_Hh + o) =
                    __halves2half2(__float2half_rn(v0), __float2half_rn(v1));
            }
        }
}

// ---------------- GEMM2: H @ Wd^T -> scatter fp32 ----------------
__global__ void __launch_bounds__(512, 1) k_gemm2(float* out) {
    extern __shared__ __align__(1024) char smem[];
    int nt = blockIdx.x, mtb = blockIdx.y * 128;
    if (mtb >= g_meta[5]) return;
    int e = (mtb >= g_meta[4]) ? 1 : 0;
    int tid = threadIdx.x, lane = tid & 31, wid = tid >> 5;
    int mw = wid & 3, nw = wid >> 2;
    int pb[4] = {nw * 64, nw * 64 + 16, nw * 64 + 32, nw * 64 + 48};
    const __half* Bd = g_Wd + ((size_t)e * DD + (size_t)nt * 256) * FF;
    float acc[2][8][4];
    gemm_main(g_Hh + (size_t)mtb * FF,
              Bd, Bd + (size_t)128 * FF, FF, FF, FF / 64, sptr(smem), tid, pb, acc);
    #pragma unroll
    for (int mt = 0; mt < 2; mt++) {
        int row = mtb + mw * 32 + mt * 16 + (lane >> 2);
        #pragma unroll
        for (int h = 0; h < 2; h++) {
            int t = g_rows[row + h * 8];
            if (t < 0) continue;
            #pragma unroll
            for (int j = 0; j < 8; j++) {
                int col = nt * 256 + nw * 64 + j * 8 + (lane & 3) * 2;
                float2 v = make_float2(acc[mt][j][2 * h], acc[mt][j][2 * h + 1]);
                *(float2*)(out + (size_t)t * DD + col) = v;
            }
        }
    }
}

// ---------------- launch ----------------
extern "C" void kernel_launch(void* const* d_in, const int* in_sizes, int n_in,
                              void* d_out, int out_size) {
    const float* X = (const float*)d_in[0];
    const int* mask = (const int*)d_in[1];
    const float* wg = (const float*)d_in[2];
    const float* wu = (const float*)d_in[3];
    const float* wd = (const float*)d_in[4];
    float* out = (float*)d_out;

    cudaFuncSetAttribute(k_gemm1, cudaFuncAttributeMaxDynamicSharedMemorySize, 2 * STAGE);
    cudaFuncSetAttribute(k_gemm2, cudaFuncAttributeMaxDynamicSharedMemorySize, 2 * STAGE);

    void *pWg, *pWu, *pWd;
    cudaGetSymbolAddress(&pWg, g_Wg);
    cudaGetSymbolAddress(&pWu, g_Wu);
    cudaGetSymbolAddress(&pWd, g_Wd);

    k_init<<<(TPAD + 255) / 256, 256>>>();
    k_count<<<TOK / 256, 256>>>(mask);
    k_metak<<<1, 1>>>();
    k_assign<<<TOK / 256, 256>>>(mask);
    k_xsplit<<<(int)(((size_t)TPAD * DD / 4 + 255) / 256), 256>>>(X);
    k_tr<<<dim3(FF / 64, DD / 64, 2), 256>>>(wg, (__half*)pWg, DD, FF);
    k_tr<<<dim3(FF / 64, DD / 64, 2), 256>>>(wu, (__half*)pWu, DD, FF);
    k_tr<<<dim3(DD / 64, FF / 64, 2), 256>>>(wd, (__half*)pWd, FF, DD);
    k_gemm1<<<dim3(FF / 128, TPAD / 128), 512, 2 * STAGE>>>();
    k_gemm2<<<dim3(DD / 256, TPAD / 128), 512, 2 * STAGE>>>(out);
}